// round 17
// baseline (speedup 1.0000x reference)
#include <cuda_runtime.h>
#include <cuda_fp16.h>
#include <cstdint>

// ---------------- problem constants ----------------
#define BATCH 8
#define C 768
#define S 729               // 9^3
#define SP 736              // S padded to multiple of 32
#define NH 8
#define DH 96               // C / NH
#define HID 2048
#define NEXP 3
#define BS (BATCH * S)      // 5832 tokens
#define BH (BATCH * NH)     // 64
#define EPS 1e-5f

// weight pool offsets (elements) in transposed (N,K) fp16 pool
#define OFF_QKV  0L
#define OFF_PROJ 1769472L
#define OFF_GU   2359296L          // interleaved gate/up, stride 2*C*HID per expert
#define WSZ_GU2  3145728L
#define OFF_DOWN 11796480L
#define WSZ_DN   1572864L
#define WPOOL    16515072L

// ---------------- static device scratch (no allocs allowed) ----------------
__device__ __half g_tok1h[(long)BS * C];
__device__ float g_attn[(long)BH * S * SP];               // scores, padded cols
__device__ __half g_ph[(long)BH * S * SP];
__device__ __half g_qh[(long)BH * S * DH];
__device__ __half g_kh[(long)BH * S * DH];
__device__ __half g_vth[(long)BH * DH * SP];
__device__ __half g_oh[(long)BS * C];
__device__ float g_tok2[(long)BS * C];
__device__ __half g_tok2h[(long)BS * C];
__device__ __half g_hid[(long)NEXP * BS * HID];           // per-expert hid
__device__ float g_moe2[(long)BS * 2 * C];                // per-token slot outputs
__device__ float g_w   [(long)BS * NEXP];
__device__ float g_stats[BATCH * 2];
__device__ __half g_wt[WPOOL];                            // weights fp16
// MoE routing lists
__device__ int g_cnt[NEXP];
__device__ int g_tlist[NEXP * BS];                        // encoded t*2 + slot
__device__ __half g_ag[(long)NEXP * BS * C];              // per-expert gathered A

__device__ __forceinline__ void mma16816(float* c, const uint32_t* a, const uint32_t* b) {
    asm volatile(
        "mma.sync.aligned.m16n8k16.row.col.f32.f16.f16.f32 "
        "{%0,%1,%2,%3}, {%4,%5,%6,%7}, {%8,%9}, {%0,%1,%2,%3};"
        : "+f"(c[0]), "+f"(c[1]), "+f"(c[2]), "+f"(c[3])
        : "r"(a[0]), "r"(a[1]), "r"(a[2]), "r"(a[3]), "r"(b[0]), "r"(b[1]));
}

__device__ __forceinline__ void ldsm4(uint32_t* r, uint32_t addr) {
    asm volatile("ldmatrix.sync.aligned.m8n8.x4.shared.b16 {%0,%1,%2,%3}, [%4];"
                 : "=r"(r[0]), "=r"(r[1]), "=r"(r[2]), "=r"(r[3]) : "r"(addr));
}

// ================== weight transpose+convert: W(K,N) fp32 -> Wt(N,K) fp16 ==================
// grid.z selects expert: W += z*wstride, th += z*tstride
__global__ void wconv_kernel(const float* __restrict__ W,
                             __half* __restrict__ th,
                             int K, int N, int mul, int add,
                             long wstride, long tstride) {
    __shared__ float t[32][33];
    W  += (long)blockIdx.z * wstride;
    th += (long)blockIdx.z * tstride;
    int nt = blockIdx.x * 32, kt = blockIdx.y * 32;
    int tx = threadIdx.x & 31, ty = threadIdx.x >> 5;
    for (int r = ty; r < 32; r += 8)
        t[r][tx] = W[(long)(kt + r) * N + nt + tx];
    __syncthreads();
    for (int r = ty; r < 32; r += 8) {
        long o = ((long)(nt + r) * mul + add) * K + kt + tx;
        th[o] = __float2half_rn(t[tx][r]);
    }
}

// ================== epilogue dispatch ==================
// EPI: 0=store, 2=qkv split, 3=swiglu(list), 4=proj+residual, 5=fp16 out, 6=moe scatter
template<int EPI>
__device__ __forceinline__ void epi_store(
    int row, int col, float x, float y, int ldc,
    float* Cm, __half* Eh,
    const float* Xaux, float* Faux, const float* Wrow, int eidx, const int* Tl)
{
    if (EPI == 0) {
        *reinterpret_cast<float2*>(Cm + (long)row * ldc + col) = make_float2(x, y);
    } else if (EPI == 2) {
        int b = row / S, s = row - b * S;
        int which = col / C;
        int hd = col - which * C;
        int h = hd / DH, d = hd - h * DH;
        if (which == 2) {
            long o = ((long)(b * NH + h) * DH + d) * SP + s;
            g_vth[o] = __float2half_rn(x);
            g_vth[o + SP] = __float2half_rn(y);
        } else {
            long o = ((long)(b * NH + h) * S + s) * DH + d;
            __half* H = which ? g_kh : g_qh;
            H[o] = __float2half_rn(x);
            H[o + 1] = __float2half_rn(y);
        }
    } else if (EPI == 3) {
        int te = Tl[row] >> 1;
        float w = Wrow[te * 3 + eidx];
        float sig = 1.f / (1.f + __expf(-x));
        float v = x * sig * y * w;
        long o = (long)row * HID + (col >> 1);
        Eh[o] = __float2half_rn(v);
    } else if (EPI == 4) {
        int b = row / S, s = row - b * S;
        long xo = ((long)b * C + col) * S + s;
        float v0 = x + Xaux[xo];
        float v1 = y + Xaux[xo + S];
        Faux[xo] = v0; Faux[xo + S] = v1;
        *reinterpret_cast<float2*>(Cm + (long)row * ldc + col) = make_float2(v0, v1);
        Eh[(long)row * ldc + col] = __float2half_rn(v0);
        Eh[(long)row * ldc + col + 1] = __float2half_rn(v1);
    } else if (EPI == 5) {
        Eh[(long)row * ldc + col] = __float2half_rn(x);
        Eh[(long)row * ldc + col + 1] = __float2half_rn(y);
    } else {  // 6: MoE scatter to slot buffer
        int enc = Tl[row];
        int t = enc >> 1, slot = enc & 1;
        *reinterpret_cast<float2*>(Cm + ((long)t * 2 + slot) * C + col) = make_float2(x, y);
    }
}

// ================== 3-stage pipelined HMMA fp16 GEMM ==================
// 128-thread CTAs, 4 warps as 2x2 of 64x64 warp tiles, 3 CTAs/SM.
#define LDT 20
#define TSZ (128 * LDT)
#define STAGES 3

__device__ __forceinline__ void load_chunks(
    uint32_t sb32, int stage, int k0, int tid, int m0, int n0, int M, int N,
    int lda, int ldb,
    const __half* __restrict__ Ah, const __half* __restrict__ Bh)
{
#pragma unroll
    for (int j = 0; j < 8; j++) {
        int c = tid + j * 128;
        int mat = c >> 9;          // 0:A 1:B
        int idx = c & 511;
        int row = idx >> 2;
        int seg = idx & 3;
        const __half* g;
        int vb = 16;
        if (mat == 0) {
            int r = m0 + row;
            if (r >= M) { r = M - 1; vb = 0; }
            g = Ah + (long)r * lda;
        } else {
            int r = n0 + row;
            if (r >= N) { r = N - 1; vb = 0; }
            g = Bh + (long)r * ldb;
        }
        g += k0 + seg * 8;
        uint32_t dst = sb32 + (uint32_t)((stage * 2 * TSZ + mat * TSZ + row * LDT + seg * 4) * 4);
        asm volatile("cp.async.ca.shared.global [%0], [%1], 16, %2;"
                     :: "r"(dst), "l"(g), "r"(vb) : "memory");
    }
}

template<int EPI>
__global__ void __launch_bounds__(128, 3)
hmma4_gemm_kernel(const __half* __restrict__ Ah, const __half* __restrict__ Bh,
                  float* __restrict__ Cm, __half* __restrict__ Eh,
                  const float* __restrict__ Xaux, float* __restrict__ Faux,
                  const float* __restrict__ Wrow, int eidx,
                  const int* __restrict__ Mdyn, const int* __restrict__ Tl,
                  int M, int N, int K, int lda, int ldb, int ldc,
                  long sA1, long sA2, long sB1, long sB2, long sC1, long sC2, int div)
{
    extern __shared__ uint32_t smp[];
    int z = blockIdx.z;
    int z1 = z / div, z2 = z % div;
    if (Mdyn) { M = Mdyn[z1]; Tl += (long)z1 * BS; }
    const int m0 = blockIdx.y * 128;
    if (m0 >= M) return;
    const int tid = threadIdx.x;
    const int lane = tid & 31;
    const int w = tid >> 5;            // 0..3
    const int wm = w & 1;              // 2 m-groups of 64
    const int wn = w >> 1;             // 2 n-groups of 64
    const int gid = lane >> 2;
    const int tig = lane & 3;
    const int n0 = blockIdx.x * 128;
    uint32_t sb32 = (uint32_t)__cvta_generic_to_shared(smp);

    Ah += z1 * sA1 + z2 * sA2;
    Bh += z1 * sB1 + z2 * sB2;
    Cm += z1 * sC1 + z2 * sC2;
    if (EPI == 5) { Eh += z1 * sC1 + z2 * sC2; }
    if (EPI == 3) { Eh += (long)z1 * BS * HID; eidx = z1; }

    // ldmatrix per-lane row offsets (u32 units within a tile)
    const int la7 = lane & 7;
    const uint32_t a_off = (uint32_t)((wm * 64 + la7 + ((lane >> 3) & 1) * 8) * LDT + (lane >> 4) * 4);
    const uint32_t b_off = (uint32_t)((wn * 64 + la7 + ((lane >> 4) & 1) * 8) * LDT + ((lane >> 3) & 1) * 4);

    float acc[4][8][4];
#pragma unroll
    for (int i = 0; i < 4; i++)
#pragma unroll
        for (int j = 0; j < 8; j++)
#pragma unroll
            for (int q = 0; q < 4; q++) acc[i][j][q] = 0.f;

    const int NKB = K >> 5;

    // prologue: up to 2 stages in flight
#pragma unroll
    for (int s = 0; s < 2; s++) {
        if (s < NKB) {
            load_chunks(sb32, s, s << 5, tid, m0, n0, M, N, lda, ldb, Ah, Bh);
            asm volatile("cp.async.commit_group;" ::: "memory");
        }
    }

    int cur = 0;
    for (int kb = 0; kb < NKB; kb++) {
        if (kb + 1 < NKB) asm volatile("cp.async.wait_group 1;" ::: "memory");
        else              asm volatile("cp.async.wait_group 0;" ::: "memory");
        __syncthreads();

        if (kb + 2 < NKB) {
            int ls = cur + 2; if (ls >= STAGES) ls -= STAGES;
            load_chunks(sb32, ls, (kb + 2) << 5, tid, m0, n0, M, N, lda, ldb, Ah, Bh);
            asm volatile("cp.async.commit_group;" ::: "memory");
        }

        const uint32_t stg = sb32 + (uint32_t)(cur * 2 * TSZ * 4);

#pragma unroll
        for (int k16 = 0; k16 < 2; k16++) {
            const uint32_t kb8 = (uint32_t)(k16 * 8);
            uint32_t ahi[4][4];
            {
                uint32_t aaddr = stg + (a_off + kb8) * 4;
#pragma unroll
                for (int mt = 0; mt < 4; mt++)
                    ldsm4(ahi[mt], aaddr + (uint32_t)(mt * 16 * LDT) * 4);
            }
#pragma unroll
            for (int ntp = 0; ntp < 4; ntp++) {
                uint32_t bq[4];
                ldsm4(bq, stg + TSZ * 4 + (b_off + (uint32_t)(ntp * 16 * LDT) + kb8) * 4);
#pragma unroll
                for (int mt = 0; mt < 4; mt++) {
                    mma16816(acc[mt][ntp * 2],     ahi[mt], bq);
                    mma16816(acc[mt][ntp * 2 + 1], ahi[mt], bq + 2);
                }
            }
        }
        if (++cur == STAGES) cur = 0;
        // single sync per iter: next iteration's barrier protects stage reuse
    }

    // ---- fused epilogue ----
#pragma unroll
    for (int mt = 0; mt < 4; mt++) {
        int row = m0 + wm * 64 + mt * 16 + gid;
#pragma unroll
        for (int nt = 0; nt < 8; nt++) {
            int col = n0 + wn * 64 + nt * 8 + tig * 2;
            if (col >= N) continue;
            if (row < M)
                epi_store<EPI>(row, col, acc[mt][nt][0], acc[mt][nt][1], ldc,
                               Cm, Eh, Xaux, Faux, Wrow, eidx, Tl);
            if (row + 8 < M)
                epi_store<EPI>(row + 8, col, acc[mt][nt][2], acc[mt][nt][3], ldc,
                               Cm, Eh, Xaux, Faux, Wrow, eidx, Tl);
        }
    }
}

// ---------------- LayerNorm statistics (also zero MoE counters) ----------------
__global__ void stats_kernel(const float* __restrict__ x) {
    int b = blockIdx.x;
    if (b == 0 && threadIdx.x < NEXP) g_cnt[threadIdx.x] = 0;
    const float* xb = x + (long)b * C * S;
    const int N = C * S;
    float s = 0.f, s2 = 0.f;
    for (int i = threadIdx.x; i < N; i += blockDim.x) {
        float v = xb[i];
        s += v; s2 += v * v;
    }
    __shared__ float sh[256], sh2[256];
    int tid = threadIdx.x;
    sh[tid] = s; sh2[tid] = s2;
    __syncthreads();
    for (int st = 128; st > 0; st >>= 1) {
        if (tid < st) { sh[tid] += sh[tid + st]; sh2[tid] += sh2[tid + st]; }
        __syncthreads();
    }
    if (tid == 0) {
        float m = sh[0] / (float)N;
        g_stats[b * 2 + 0] = m;
        g_stats[b * 2 + 1] = sh2[0] / (float)N - m * m;
    }
}

// ---------------- LN apply + transpose + fp16 ----------------
__global__ void ln_kernel(const float* __restrict__ x,
                          const float* __restrict__ w,
                          const float* __restrict__ bia) {
    long idx = (long)blockIdx.x * blockDim.x + threadIdx.x;
    if (idx >= (long)BATCH * C * S) return;
    int b   = (int)(idx / ((long)C * S));
    int rem = (int)(idx % ((long)C * S));
    int c = rem / S, s = rem % S;
    float m   = g_stats[b * 2 + 0];
    float var = g_stats[b * 2 + 1];
    float y = (x[idx] - m) * rsqrtf(var + EPS) * w[rem] + bia[rem];
    g_tok1h[((long)b * S + s) * C + c] = __float2half_rn(y);
}

// ---------------- fused one-pass softmax -> fp16 P (padded) ----------------
__global__ void softmax_bf_kernel() {
    long row = blockIdx.x;                    // BH * S rows
    const float* p = g_attn + row * SP;
    __half* ph = g_ph + row * SP;
    int tid = threadIdx.x;
    __shared__ float sw[8];

    int i2 = tid + 512;
    float v0 = p[tid];
    float v1 = p[tid + 256];
    float v2 = (i2 < S) ? p[i2] : -1e30f;

    float mx = fmaxf(v0, fmaxf(v1, v2));
#pragma unroll
    for (int o = 16; o > 0; o >>= 1) mx = fmaxf(mx, __shfl_xor_sync(~0u, mx, o));
    if ((tid & 31) == 0) sw[tid >> 5] = mx;
    __syncthreads();
    if (tid < 32) {
        float m = (tid < 8) ? sw[tid] : -1e30f;
#pragma unroll
        for (int o = 4; o > 0; o >>= 1) m = fmaxf(m, __shfl_xor_sync(~0u, m, o));
        if (tid == 0) sw[0] = m;
    }
    __syncthreads();
    mx = sw[0];
    __syncthreads();

    float e0 = __expf(v0 - mx);
    float e1 = __expf(v1 - mx);
    float e2 = (i2 < S) ? __expf(v2 - mx) : 0.f;
    float sum = e0 + e1 + e2;
#pragma unroll
    for (int o = 16; o > 0; o >>= 1) sum += __shfl_xor_sync(~0u, sum, o);
    if ((tid & 31) == 0) sw[tid >> 5] = sum;
    __syncthreads();
    if (tid < 32) {
        float s = (tid < 8) ? sw[tid] : 0.f;
#pragma unroll
        for (int o = 4; o > 0; o >>= 1) s += __shfl_xor_sync(~0u, s, o);
        if (tid == 0) sw[0] = s;
    }
    __syncthreads();
    float inv = 1.f / sw[0];

    ph[tid]       = __float2half_rn(e0 * inv);
    ph[tid + 256] = __float2half_rn(e1 * inv);
    if (i2 < SP)
        ph[i2] = __float2half_rn((i2 < S) ? e2 * inv : 0.f);
}

// ---------------- router: weights + per-expert token lists ----------------
__global__ void router_kernel(const float* __restrict__ rw) {
    int t = blockIdx.x * blockDim.y + threadIdx.y;
    if (t >= BS) return;
    const float* tok = g_tok2 + (long)t * C;
    float l0 = 0.f, l1 = 0.f, l2 = 0.f;
    for (int c = threadIdx.x; c < C; c += 32) {
        float v = tok[c];
        l0 += v * rw[c * 3 + 0];
        l1 += v * rw[c * 3 + 1];
        l2 += v * rw[c * 3 + 2];
    }
#pragma unroll
    for (int off = 16; off > 0; off >>= 1) {
        l0 += __shfl_down_sync(0xFFFFFFFFu, l0, off);
        l1 += __shfl_down_sync(0xFFFFFFFFu, l1, off);
        l2 += __shfl_down_sync(0xFFFFFFFFu, l2, off);
    }
    if (threadIdx.x == 0) {
        float mx = fmaxf(l0, fmaxf(l1, l2));
        float e0 = __expf(l0 - mx), e1 = __expf(l1 - mx), e2 = __expf(l2 - mx);
        float tot = e0 + e1 + e2;
        float p[3] = { e0 / tot, e1 / tot, e2 / tot };
        int i1 = 0;
        if (p[1] > p[i1]) i1 = 1;
        if (p[2] > p[i1]) i1 = 2;
        int i2 = -1;
        for (int i = 0; i < 3; i++) {
            if (i == i1) continue;
            if (i2 < 0 || p[i] > p[i2]) i2 = i;
        }
        float den = p[i1] + p[i2];
        float w[3] = { 0.f, 0.f, 0.f };
        w[i1] = p[i1] / den;
        w[i2] = p[i2] / den;
        g_w[t * 3 + 0] = w[0];
        g_w[t * 3 + 1] = w[1];
        g_w[t * 3 + 2] = w[2];
        int p1 = atomicAdd(&g_cnt[i1], 1);
        g_tlist[i1 * BS + p1] = t * 2;
        int p2 = atomicAdd(&g_cnt[i2], 1);
        g_tlist[i2 * BS + p2] = t * 2 + 1;
    }
}

// ---------------- gather tok2 fp16 rows for all experts (grid.y = e) ----------------
__global__ void gather_kernel() {
    int e = blockIdx.y;
    int p = blockIdx.x * 8 + (threadIdx.x >> 5);
    if (p >= g_cnt[e]) return;
    int t = g_tlist[e * BS + p] >> 1;
    int lane = threadIdx.x & 31;
    const uint32_t* sh = reinterpret_cast<const uint32_t*>(g_tok2h + (long)t * C);
    uint32_t* dh = reinterpret_cast<uint32_t*>(g_ag + ((long)e * BS + p) * C);
#pragma unroll
    for (int i = 0; i < 12; i++)
        dh[lane + i * 32] = sh[lane + i * 32];
}

// ---------------- out(b,c,s) += slot0 + slot1 ----------------
__global__ void final_kernel(float* __restrict__ out) {
    long idx = (long)blockIdx.x * blockDim.x + threadIdx.x;
    if (idx >= (long)BATCH * C * S) return;
    int b   = (int)(idx / ((long)C * S));
    int rem = (int)(idx % ((long)C * S));
    int c = rem / S, s = rem % S;
    long t = (long)b * S + s;
    out[idx] += g_moe2[t * 2 * C + c] + g_moe2[t * 2 * C + C + c];
}

// ---------------- launcher ----------------
extern "C" void kernel_launch(void* const* d_in, const int* in_sizes, int n_in,
                              void* d_out, int out_size) {
    const float* x        = (const float*)d_in[0];
    const float* ln_w     = (const float*)d_in[1];
    const float* ln_b     = (const float*)d_in[2];
    const float* qkv_w    = (const float*)d_in[3];
    const float* proj_w   = (const float*)d_in[4];
    const float* router_w = (const float*)d_in[5];
    const float* gate_w   = (const float*)d_in[6];
    const float* up_w     = (const float*)d_in[7];
    const float* down_w   = (const float*)d_in[8];
    float* out = (float*)d_out;

    float *p_attn, *p_tok2, *p_moe2, *p_gw;
    __half *p_t1h, *p_oh, *p_t2h, *p_hid, *p_wt;
    __half *p_ph, *p_qh, *p_kh, *p_vth, *p_ag;
    int *p_cnt, *p_tlist;
    cudaGetSymbolAddress((void**)&p_attn, g_attn);
    cudaGetSymbolAddress((void**)&p_tok2, g_tok2);
    cudaGetSymbolAddress((void**)&p_moe2, g_moe2);
    cudaGetSymbolAddress((void**)&p_gw,   g_w);
    cudaGetSymbolAddress((void**)&p_t1h, g_tok1h);
    cudaGetSymbolAddress((void**)&p_oh,  g_oh);
    cudaGetSymbolAddress((void**)&p_t2h, g_tok2h);
    cudaGetSymbolAddress((void**)&p_hid, g_hid);
    cudaGetSymbolAddress((void**)&p_wt,  g_wt);
    cudaGetSymbolAddress((void**)&p_ph,  g_ph);
    cudaGetSymbolAddress((void**)&p_qh,  g_qh);
    cudaGetSymbolAddress((void**)&p_kh,  g_kh);
    cudaGetSymbolAddress((void**)&p_vth, g_vth);
    cudaGetSymbolAddress((void**)&p_ag,  g_ag);
    cudaGetSymbolAddress((void**)&p_cnt, g_cnt);
    cudaGetSymbolAddress((void**)&p_tlist, g_tlist);

    const int SMEM_GEMM = STAGES * 2 * TSZ * 4;   // 61440 B
    cudaFuncSetAttribute(hmma4_gemm_kernel<0>, cudaFuncAttributeMaxDynamicSharedMemorySize, SMEM_GEMM);
    cudaFuncSetAttribute(hmma4_gemm_kernel<2>, cudaFuncAttributeMaxDynamicSharedMemorySize, SMEM_GEMM);
    cudaFuncSetAttribute(hmma4_gemm_kernel<3>, cudaFuncAttributeMaxDynamicSharedMemorySize, SMEM_GEMM);
    cudaFuncSetAttribute(hmma4_gemm_kernel<4>, cudaFuncAttributeMaxDynamicSharedMemorySize, SMEM_GEMM);
    cudaFuncSetAttribute(hmma4_gemm_kernel<5>, cudaFuncAttributeMaxDynamicSharedMemorySize, SMEM_GEMM);
    cudaFuncSetAttribute(hmma4_gemm_kernel<6>, cudaFuncAttributeMaxDynamicSharedMemorySize, SMEM_GEMM);

    const long n_elem = (long)BATCH * C * S;
    const int MT = (BS + 127) / 128;   // 46 row tiles

    // 1) qkv weight conversion first
    wconv_kernel<<<dim3(3 * C / 32, C / 32, 1), 256>>>(qkv_w, p_wt + OFF_QKV, C, 3 * C, 1, 0, 0, 0);

    // 2-3) LayerNorm (+ counter reset)
    stats_kernel<<<BATCH, 256>>>(x);
    ln_kernel<<<(int)((n_elem + 255) / 256), 256>>>(x, ln_w, ln_b);

    // 4) qkv GEMM with fused q/k/v split epilogue
    hmma4_gemm_kernel<2><<<dim3(3 * C / 128, MT, 1), 128, SMEM_GEMM>>>(
        p_t1h, p_wt + OFF_QKV,
        nullptr, nullptr, nullptr, nullptr, nullptr, 0, nullptr, nullptr,
        BS, 3 * C, C, C, C, 0, 0, 0, 0, 0, 0, 0, 1);

    // 5) scores: per (b,h) 729x729 = q @ k^T
    hmma4_gemm_kernel<0><<<dim3(6, 6, BH), 128, SMEM_GEMM>>>(
        p_qh, p_kh,
        p_attn, nullptr, nullptr, nullptr, nullptr, 0, nullptr, nullptr,
        S, S, DH, DH, DH, SP,
        (long)NH * S * DH, (long)S * DH,
        (long)NH * S * DH, (long)S * DH,
        (long)NH * S * SP, (long)S * SP, NH);

    // 6) softmax -> fp16 P
    softmax_bf_kernel<<<BH * S, 256>>>();

    // 7-10) remaining weight conversions (batched over experts)
    wconv_kernel<<<dim3(C / 32, C / 32, 1), 256>>>(proj_w, p_wt + OFF_PROJ, C, C, 1, 0, 0, 0);
    wconv_kernel<<<dim3(HID / 32, C / 32, NEXP), 256>>>(
        gate_w, p_wt + OFF_GU, C, HID, 2, 0, (long)C * HID, WSZ_GU2);
    wconv_kernel<<<dim3(HID / 32, C / 32, NEXP), 256>>>(
        up_w,   p_wt + OFF_GU, C, HID, 2, 1, (long)C * HID, WSZ_GU2);
    wconv_kernel<<<dim3(C / 32, HID / 32, NEXP), 256>>>(
        down_w, p_wt + OFF_DOWN, HID, C, 1, 0, (long)HID * C, WSZ_DN);

    // PV: per (b,h) 729x96 = P @ V, fp16 out
    hmma4_gemm_kernel<5><<<dim3(1, 6, BH), 128, SMEM_GEMM>>>(
        p_ph, p_vth,
        nullptr, p_oh, nullptr, nullptr, nullptr, 0, nullptr, nullptr,
        S, DH, SP, SP, SP, C,
        (long)NH * S * SP, (long)S * SP,
        (long)NH * DH * SP, (long)DH * SP,
        (long)S * C, DH, NH);

    // proj GEMM + fused residual (writes out, tok2 fp32 + fp16)
    hmma4_gemm_kernel<4><<<dim3(C / 128, MT, 1), 128, SMEM_GEMM>>>(
        p_oh, p_wt + OFF_PROJ,
        p_tok2, p_t2h, x, out, nullptr, 0, nullptr, nullptr,
        BS, C, C, C, C, C, 0, 0, 0, 0, 0, 0, 1);

    // router (weights + token lists)
    {
        dim3 blk(32, 8);
        router_kernel<<<(BS + 7) / 8, blk>>>(router_w);
    }

    // MoE: one gather, one gate/up GEMM, one down GEMM (all batched over experts)
    gather_kernel<<<dim3((BS + 7) / 8, NEXP), 256>>>();

    hmma4_gemm_kernel<3><<<dim3(2 * HID / 128, MT, NEXP), 128, SMEM_GEMM>>>(
        p_ag, p_wt + OFF_GU,
        nullptr, p_hid, nullptr, nullptr, p_gw, 0, p_cnt, p_tlist,
        BS, 2 * HID, C, C, C, 0,
        (long)BS * C, 0, WSZ_GU2, 0, 0, 0, 1);

    hmma4_gemm_kernel<6><<<dim3(C / 128, MT, NEXP), 128, SMEM_GEMM>>>(
        p_hid, p_wt + OFF_DOWN,
        p_moe2, nullptr, nullptr, nullptr, nullptr, 0, p_cnt, p_tlist,
        BS, C, HID, HID, HID, C,
        (long)BS * HID, 0, WSZ_DN, 0, 0, 0, 1);

    // final add
    final_kernel<<<(int)((n_elem + 255) / 256), 256>>>(out);
}